// round 1
// baseline (speedup 1.0000x reference)
#include <cuda_runtime.h>
#include <math.h>

// ---------------- problem constants ----------------
#define BB       2
#define IMG      512
#define PS       16
#define HP       32          // Hp = Wp = 32
#define NTOK     1024        // HP*HP
#define CDIM     768
#define NHEADS   12
#define HEADD    64
#define NPTS     4
#define SCALE_F  0.125f      // HEAD^-0.5
#define EPS_F    1e-6f
#define MROWS    (BB*NTOK)   // 2048

// ---------------- device scratch (no allocations allowed) ----------------
__device__ float g_x   [MROWS*CDIM];
__device__ float g_h   [MROWS*CDIM];
__device__ float g_qkv [MROWS*3*CDIM];
__device__ float g_col [MROWS*CDIM];
__device__ float g_offs[MROWS*96];
__device__ float g_ao  [MROWS*CDIM];
__device__ float g_sc  [(size_t)BB*NHEADS*NTOK*NTOK];
__device__ float g_mlp [MROWS*4*CDIM];

// ---------------- helpers ----------------
__device__ __forceinline__ float gelu_f(float v) {
    return 0.5f * v * (1.0f + erff(v * 0.7071067811865476f));
}

// =====================================================================
// Generic tiled FP32 GEMM:  C = epi( A(MxK) * op(B) + bias )
//   TRANS_B=true : B is (N,K) row-major  -> C = A * B^T
//   TRANS_B=false: B is (K,N) row-major  -> C = A * B
// Batched via blockIdx.z: z -> (b = z/nh, h = z%nh), offsets b*s?b + h*s?h
// epi: 0 = bias only, 1 = gelu(bias), 2 = residual C += (acc + bias)
// Requires M % 64 == 0, K % 16 == 0 (N guarded).
// =====================================================================
#define BM 64
#define BN 64
#define BK 16

template<bool TRANS_B>
__global__ void gemm_kernel(const float* __restrict__ A, const float* __restrict__ B,
                            float* __restrict__ C, const float* __restrict__ bias,
                            int M, int N, int K, int lda, int ldb, int ldc,
                            long sAb, long sAh, long sBb, long sBh, long sCb, long sCh,
                            int nh, int epi)
{
    int z  = blockIdx.z;
    int bb = z / nh, hh = z % nh;
    A += (long)bb * sAb + (long)hh * sAh;
    B += (long)bb * sBb + (long)hh * sBh;
    C += (long)bb * sCb + (long)hh * sCh;

    const int m0 = blockIdx.y * BM;
    const int n0 = blockIdx.x * BN;

    __shared__ float As[BK][BM];
    __shared__ float Bs[BK][BN];

    const int tid = threadIdx.x;          // 256 threads
    const int tx  = tid & 15;             // N direction
    const int ty  = tid >> 4;             // M direction

    float acc[4][4] = {};

    for (int k0 = 0; k0 < K; k0 += BK) {
        // --- load A tile (64x16), float4 along K ---
        {
            int m  = tid >> 2;
            int kq = (tid & 3) * 4;
            float4 v = *(const float4*)(A + (long)(m0 + m) * lda + (k0 + kq));
            As[kq + 0][m] = v.x; As[kq + 1][m] = v.y;
            As[kq + 2][m] = v.z; As[kq + 3][m] = v.w;
        }
        // --- load B tile ---
        if (TRANS_B) {
            int n  = tid >> 2;
            int kq = (tid & 3) * 4;
            float4 v = make_float4(0.f, 0.f, 0.f, 0.f);
            if (n0 + n < N)
                v = *(const float4*)(B + (long)(n0 + n) * ldb + (k0 + kq));
            Bs[kq + 0][n] = v.x; Bs[kq + 1][n] = v.y;
            Bs[kq + 2][n] = v.z; Bs[kq + 3][n] = v.w;
        } else {
            int n = (tid & 15) * 4;
            int k = tid >> 4;
            float4 v;
            const float* brow = B + (long)(k0 + k) * ldb;
            if (n0 + n + 3 < N) {
                v = *(const float4*)(brow + n0 + n);
            } else {
                v.x = (n0 + n     < N) ? brow[n0 + n    ] : 0.f;
                v.y = (n0 + n + 1 < N) ? brow[n0 + n + 1] : 0.f;
                v.z = (n0 + n + 2 < N) ? brow[n0 + n + 2] : 0.f;
                v.w = (n0 + n + 3 < N) ? brow[n0 + n + 3] : 0.f;
            }
            *(float4*)&Bs[k][n] = v;
        }
        __syncthreads();

        #pragma unroll
        for (int kk = 0; kk < BK; kk++) {
            float4 a4 = *(const float4*)&As[kk][ty * 4];
            float4 b4 = *(const float4*)&Bs[kk][tx * 4];
            float a[4] = {a4.x, a4.y, a4.z, a4.w};
            float b[4] = {b4.x, b4.y, b4.z, b4.w};
            #pragma unroll
            for (int i = 0; i < 4; i++)
                #pragma unroll
                for (int j = 0; j < 4; j++)
                    acc[i][j] += a[i] * b[j];
        }
        __syncthreads();
    }

    // --- epilogue ---
    #pragma unroll
    for (int i = 0; i < 4; i++) {
        int m = m0 + ty * 4 + i;
        #pragma unroll
        for (int j = 0; j < 4; j++) {
            int n = n0 + tx * 4 + j;
            if (n < N) {
                float v = acc[i][j];
                if (bias) v += bias[n];
                if (epi == 1) v = gelu_f(v);
                long idx = (long)m * ldc + n;
                if (epi == 2) v += C[idx];
                C[idx] = v;
            }
        }
    }
}

// =====================================================================
// im2col for patch embed: col[(b*N+n), ci*256+ky*16+kx]
// =====================================================================
__global__ void im2col_kernel(const float* __restrict__ x, float* __restrict__ col)
{
    long idx = (long)blockIdx.x * blockDim.x + threadIdx.x;
    if (idx >= (long)MROWS * CDIM) return;
    int k = (int)(idx % CDIM);
    int m = (int)(idx / CDIM);
    int b  = m >> 10;
    int n  = m & 1023;
    int hp = n >> 5, wp = n & 31;
    int ci = k >> 8;
    int r  = k & 255;
    int ky = r >> 4, kx = r & 15;
    long src = (((long)(b * 3 + ci) * IMG) + hp * PS + ky) * IMG + wp * PS + kx;
    col[idx] = x[src];
}

// =====================================================================
// LayerNorm: one block (256 thr) per token row of 768
// =====================================================================
__global__ void layernorm_kernel(const float* __restrict__ in, float* __restrict__ out,
                                 const float* __restrict__ s, const float* __restrict__ b)
{
    __shared__ float red[8];
    const long row = blockIdx.x;
    const float* r = in + row * CDIM;
    float* o = out + row * CDIM;
    int tid = threadIdx.x, lane = tid & 31, w = tid >> 5;

    float v[3];
    float sum = 0.f;
    #pragma unroll
    for (int j = 0; j < 3; j++) { v[j] = r[tid + j * 256]; sum += v[j]; }
    #pragma unroll
    for (int off = 16; off; off >>= 1) sum += __shfl_xor_sync(~0u, sum, off);
    if (lane == 0) red[w] = sum;
    __syncthreads();
    if (w == 0) {
        float t = (lane < 8) ? red[lane] : 0.f;
        #pragma unroll
        for (int off = 4; off; off >>= 1) t += __shfl_xor_sync(~0u, t, off);
        if (lane == 0) red[0] = t;
    }
    __syncthreads();
    float mu = red[0] * (1.f / CDIM);
    __syncthreads();

    float sq = 0.f;
    #pragma unroll
    for (int j = 0; j < 3; j++) { float d = v[j] - mu; sq += d * d; }
    #pragma unroll
    for (int off = 16; off; off >>= 1) sq += __shfl_xor_sync(~0u, sq, off);
    if (lane == 0) red[w] = sq;
    __syncthreads();
    if (w == 0) {
        float t = (lane < 8) ? red[lane] : 0.f;
        #pragma unroll
        for (int off = 4; off; off >>= 1) t += __shfl_xor_sync(~0u, t, off);
        if (lane == 0) red[0] = t;
    }
    __syncthreads();
    float rstd = rsqrtf(red[0] * (1.f / CDIM) + EPS_F);

    #pragma unroll
    for (int j = 0; j < 3; j++) {
        int c = tid + j * 256;
        o[c] = (v[j] - mu) * rstd * s[c] + b[c];
    }
}

// =====================================================================
// Row softmax over 1024 keys, with scale (full attention path, in-place)
// =====================================================================
__global__ void softmax_kernel(float* __restrict__ sc)
{
    __shared__ float red[8];
    float* r = sc + (long)blockIdx.x * NTOK;
    int tid = threadIdx.x, lane = tid & 31, w = tid >> 5;

    float v[4], mx = -1e30f;
    #pragma unroll
    for (int j = 0; j < 4; j++) { v[j] = r[tid + j * 256] * SCALE_F; mx = fmaxf(mx, v[j]); }
    #pragma unroll
    for (int off = 16; off; off >>= 1) mx = fmaxf(mx, __shfl_xor_sync(~0u, mx, off));
    if (lane == 0) red[w] = mx;
    __syncthreads();
    if (w == 0) {
        float t = (lane < 8) ? red[lane] : -1e30f;
        #pragma unroll
        for (int off = 4; off; off >>= 1) t = fmaxf(t, __shfl_xor_sync(~0u, t, off));
        if (lane == 0) red[0] = t;
    }
    __syncthreads();
    mx = red[0];
    __syncthreads();

    float sum = 0.f;
    #pragma unroll
    for (int j = 0; j < 4; j++) { v[j] = expf(v[j] - mx); sum += v[j]; }
    #pragma unroll
    for (int off = 16; off; off >>= 1) sum += __shfl_xor_sync(~0u, sum, off);
    if (lane == 0) red[w] = sum;
    __syncthreads();
    if (w == 0) {
        float t = (lane < 8) ? red[lane] : 0.f;
        #pragma unroll
        for (int off = 4; off; off >>= 1) t += __shfl_xor_sync(~0u, t, off);
        if (lane == 0) red[0] = t;
    }
    __syncthreads();
    float inv = 1.f / red[0];
    #pragma unroll
    for (int j = 0; j < 4; j++) r[tid + j * 256] = v[j] * inv;
}

// =====================================================================
// Fused deformable attention: one warp per (b, h, n).
// Lane handles dims d = lane and d = lane + 32.
// =====================================================================
__global__ void deform_attn_kernel(const float* __restrict__ qkv,
                                   const float* __restrict__ offs,
                                   float* __restrict__ out)
{
    int gwarp = (blockIdx.x * blockDim.x + threadIdx.x) >> 5;
    int lane  = threadIdx.x & 31;
    if (gwarp >= BB * NHEADS * NTOK) return;
    int n  = gwarp & (NTOK - 1);
    int bh = gwarp >> 10;
    int h  = bh % NHEADS;
    int b  = bh / NHEADS;
    int hp = n >> 5, wp = n & 31;

    const float* qrow = qkv + ((long)(b * NTOK + n)) * (3 * CDIM) + h * HEADD;
    float q0 = qrow[lane], q1 = qrow[lane + 32];

    const float* offrow = offs + ((long)(b * NTOK + n)) * 96 + h * NPTS * 2;

    float att[NPTS], sv0[NPTS], sv1[NPTS];

    #pragma unroll
    for (int p = 0; p < NPTS; p++) {
        float ox = offrow[p * 2 + 0];
        float oy = offrow[p * 2 + 1];
        float gx = (wp + 0.5f) * (1.f / HP) + ox * (1.f / HP);
        float gy = (hp + 0.5f) * (1.f / HP) + oy * (1.f / HP);
        float lx = 2.f * gx - 1.f;
        float ly = 2.f * gy - 1.f;
        float px = (lx + 1.f) * (HP * 0.5f) - 0.5f;
        float py = (ly + 1.f) * (HP * 0.5f) - 0.5f;
        float x0f = floorf(px), y0f = floorf(py);
        float wx = px - x0f, wy = py - y0f;
        int x0 = (int)x0f, y0 = (int)y0f;
        float cw[4] = { (1.f - wx) * (1.f - wy), wx * (1.f - wy),
                        (1.f - wx) * wy,         wx * wy };

        float k0 = 0.f, k1 = 0.f, v0 = 0.f, v1 = 0.f;
        #pragma unroll
        for (int c = 0; c < 4; c++) {
            int yi = y0 + (c >> 1);
            int xi = x0 + (c & 1);
            if (yi >= 0 && yi < HP && xi >= 0 && xi < HP) {
                const float* kr = qkv + ((long)(b * NTOK + yi * HP + xi)) * (3 * CDIM)
                                      + CDIM + h * HEADD;
                const float* vr = kr + CDIM;
                float wc = cw[c];
                k0 += wc * kr[lane];      k1 += wc * kr[lane + 32];
                v0 += wc * vr[lane];      v1 += wc * vr[lane + 32];
            }
        }
        sv0[p] = v0; sv1[p] = v1;
        float d = q0 * k0 + q1 * k1;
        #pragma unroll
        for (int off = 16; off; off >>= 1) d += __shfl_xor_sync(~0u, d, off);
        att[p] = d * SCALE_F;
    }

    float mx = fmaxf(fmaxf(att[0], att[1]), fmaxf(att[2], att[3]));
    float e[NPTS], sum = 0.f;
    #pragma unroll
    for (int p = 0; p < NPTS; p++) { e[p] = expf(att[p] - mx); sum += e[p]; }
    float inv = 1.f / sum;

    float o0 = 0.f, o1 = 0.f;
    #pragma unroll
    for (int p = 0; p < NPTS; p++) {
        float a = e[p] * inv;
        o0 += a * sv0[p];
        o1 += a * sv1[p];
    }
    float* orow = out + ((long)(b * NTOK + n)) * CDIM + h * HEADD;
    orow[lane]      = o0;
    orow[lane + 32] = o1;
}

// =====================================================================
// Output transpose: (B,N,C) -> (B,C,Hp,Wp)
// =====================================================================
__global__ void out_transpose_kernel(const float* __restrict__ x, float* __restrict__ out)
{
    long idx = (long)blockIdx.x * blockDim.x + threadIdx.x;
    if (idx >= (long)MROWS * CDIM) return;
    int n = (int)(idx % NTOK);
    int c = (int)((idx / NTOK) % CDIM);
    int b = (int)(idx / ((long)NTOK * CDIM));
    out[idx] = x[((long)(b * NTOK + n)) * CDIM + c];
}

// =====================================================================
// Host launcher
// =====================================================================
extern "C" void kernel_launch(void* const* d_in, const int* in_sizes, int n_in,
                              void* d_out, int out_size)
{
    const float* x       = (const float*)d_in[0];
    const float* patch_w = (const float*)d_in[1];
    const float* patch_b = (const float*)d_in[2];
    const float* ln1_s   = (const float*)d_in[3];
    const float* ln1_b   = (const float*)d_in[4];
    const float* qkv_w   = (const float*)d_in[5];
    const float* offs_w  = (const float*)d_in[6];
    const float* offs_b  = (const float*)d_in[7];
    const float* proj_w  = (const float*)d_in[8];
    const float* proj_b  = (const float*)d_in[9];
    const float* ln2_s   = (const float*)d_in[10];
    const float* ln2_b   = (const float*)d_in[11];
    const float* fc1_w   = (const float*)d_in[12];
    const float* fc1_b   = (const float*)d_in[13];
    const float* fc2_w   = (const float*)d_in[14];
    const float* fc2_b   = (const float*)d_in[15];

    float *gx, *gh, *gqkv, *gcol, *goffs, *gao, *gsc, *gmlp;
    cudaGetSymbolAddress((void**)&gx,   g_x);
    cudaGetSymbolAddress((void**)&gh,   g_h);
    cudaGetSymbolAddress((void**)&gqkv, g_qkv);
    cudaGetSymbolAddress((void**)&gcol, g_col);
    cudaGetSymbolAddress((void**)&goffs,g_offs);
    cudaGetSymbolAddress((void**)&gao,  g_ao);
    cudaGetSymbolAddress((void**)&gsc,  g_sc);
    cudaGetSymbolAddress((void**)&gmlp, g_mlp);

    const int M = MROWS; // 2048

    // ---- patch embed: im2col + GEMM ----
    im2col_kernel<<<(M * CDIM + 255) / 256, 256>>>(x, gcol);
    gemm_kernel<true><<<dim3(CDIM / BN, M / BM, 1), 256>>>(
        gcol, patch_w, gx, patch_b,
        M, CDIM, CDIM, CDIM, CDIM, CDIM,
        0, 0, 0, 0, 0, 0, 1, 0);

    for (int i = 0; i < 6; i++) {
        // LN1
        layernorm_kernel<<<M, 256>>>(gx, gh, ln1_s + i * CDIM, ln1_b + i * CDIM);
        // QKV (no bias)
        gemm_kernel<true><<<dim3(2304 / BN, M / BM, 1), 256>>>(
            gh, qkv_w + (long)i * 2304 * CDIM, gqkv, nullptr,
            M, 2304, CDIM, CDIM, CDIM, 2304,
            0, 0, 0, 0, 0, 0, 1, 0);

        bool sample = ((i + 1) % 3) != 0;
        if (sample) {
            // offsets = q @ offs_w^T + offs_b  (q = first 768 cols of qkv)
            gemm_kernel<true><<<dim3(2, M / BM, 1), 256>>>(
                gqkv, offs_w + (long)i * 96 * CDIM, goffs, offs_b + i * 96,
                M, 96, CDIM, 3 * CDIM, CDIM, 96,
                0, 0, 0, 0, 0, 0, 1, 0);
            deform_attn_kernel<<<(BB * NHEADS * NTOK * 32) / 256, 256>>>(gqkv, goffs, gao);
        } else {
            // scores = q @ k^T   (batched over B*NH), scale applied in softmax
            gemm_kernel<true><<<dim3(NTOK / BN, NTOK / BM, BB * NHEADS), 256>>>(
                gqkv, gqkv + CDIM, gsc, nullptr,
                NTOK, NTOK, HEADD, 3 * CDIM, 3 * CDIM, NTOK,
                (long)NTOK * 3 * CDIM, HEADD,
                (long)NTOK * 3 * CDIM, HEADD,
                (long)NHEADS * NTOK * NTOK, (long)NTOK * NTOK,
                NHEADS, 0);
            softmax_kernel<<<BB * NHEADS * NTOK, 256>>>(gsc);
            // out = P @ V   (NN)
            gemm_kernel<false><<<dim3(1, NTOK / BM, BB * NHEADS), 256>>>(
                gsc, gqkv + 2 * CDIM, gao, nullptr,
                NTOK, HEADD, NTOK, NTOK, 3 * CDIM, CDIM,
                (long)NHEADS * NTOK * NTOK, (long)NTOK * NTOK,
                (long)NTOK * 3 * CDIM, HEADD,
                (long)NTOK * CDIM, HEADD,
                NHEADS, 0);
        }

        // proj + residual into x
        gemm_kernel<true><<<dim3(CDIM / BN, M / BM, 1), 256>>>(
            gao, proj_w + (long)i * CDIM * CDIM, gx, proj_b + i * CDIM,
            M, CDIM, CDIM, CDIM, CDIM, CDIM,
            0, 0, 0, 0, 0, 0, 1, 2);

        // LN2
        layernorm_kernel<<<M, 256>>>(gx, gh, ln2_s + i * CDIM, ln2_b + i * CDIM);
        // fc1 + gelu
        gemm_kernel<true><<<dim3(3072 / BN, M / BM, 1), 256>>>(
            gh, fc1_w + (long)i * 3072 * CDIM, gmlp, fc1_b + i * 3072,
            M, 3072, CDIM, CDIM, CDIM, 3072,
            0, 0, 0, 0, 0, 0, 1, 1);
        // fc2 + residual into x
        gemm_kernel<true><<<dim3(CDIM / BN, M / BM, 1), 256>>>(
            gmlp, fc2_w + (long)i * CDIM * 3072, gx, fc2_b + i * CDIM,
            M, CDIM, 3072, 3072, 3072, CDIM,
            0, 0, 0, 0, 0, 0, 1, 2);
    }

    out_transpose_kernel<<<(M * CDIM + 255) / 256, 256>>>(gx, (float*)d_out);
}

// round 3
// speedup vs baseline: 1.9143x; 1.9143x over previous
#include <cuda_runtime.h>
#include <cuda_bf16.h>
#include <math.h>
#include <cstdint>
#include <cstddef>

// ---------------- problem constants ----------------
#define BB       2
#define IMG      512
#define PS       16
#define HP       32          // Hp = Wp = 32
#define NTOK     1024        // HP*HP
#define CDIM     768
#define NHEADS   12
#define HEADD    64
#define NPTS     4
#define SCALE_F  0.125f      // HEAD^-0.5
#define EPS_F    1e-6f
#define MROWS    (BB*NTOK)   // 2048

// ---------------- device scratch (no allocations allowed) ----------------
__device__ float g_x   [MROWS*CDIM];
__device__ float g_h   [MROWS*CDIM];
__device__ float g_qkv [MROWS*3*CDIM];
__device__ float g_col [MROWS*CDIM];
__device__ float g_offs[MROWS*96];
__device__ float g_ao  [MROWS*CDIM];
__device__ float g_sc  [(size_t)BB*NHEADS*NTOK*NTOK];
__device__ float g_mlp [MROWS*4*CDIM];

// ---------------- helpers ----------------
__device__ __forceinline__ float gelu_f(float v) {
    return 0.5f * v * (1.0f + erff(v * 0.7071067811865476f));
}

// =====================================================================
// Tensor-core GEMM (3xBF16 split for ~fp32 accuracy):
//   C = epi( A(MxK) * B(NxK)^T + bias )      [row.col mma]
// A row-major lda, B row-major ldb (N x K), C row-major ldc.
// Batched via blockIdx.z -> (b = z/nh, h = z%nh).
// epi: 0 = bias, 1 = gelu(bias), 2 = residual add.
// Requires M % 128 == 0, K % 32 == 0. N guarded.
// Block tile 128x128, BK=32, 256 threads, warp tile 64x32.
// =====================================================================
#define TBM 128
#define TBN 128
#define TBK 32
#define SPAD 40   // bf16 elements per smem row (32 + 8 pad -> conflict-free)

__global__ __launch_bounds__(256)
void mma_gemm_kernel(const float* __restrict__ A, const float* __restrict__ B,
                     float* __restrict__ C, const float* __restrict__ bias,
                     int M, int N, int K, int lda, int ldb, int ldc,
                     long sAb, long sAh, long sBb, long sBh, long sCb, long sCh,
                     int nh, int epi)
{
    int z  = blockIdx.z;
    int bb = z / nh, hh = z % nh;
    A += (long)bb * sAb + (long)hh * sAh;
    B += (long)bb * sBb + (long)hh * sBh;
    C += (long)bb * sCb + (long)hh * sCh;

    const int m0 = blockIdx.y * TBM;
    const int n0 = blockIdx.x * TBN;

    __shared__ __align__(16) __nv_bfloat16 Ah[TBM][SPAD];
    __shared__ __align__(16) __nv_bfloat16 Al[TBM][SPAD];
    __shared__ __align__(16) __nv_bfloat16 Bh[TBN][SPAD];
    __shared__ __align__(16) __nv_bfloat16 Bl[TBN][SPAD];

    const int tid   = threadIdx.x;           // 256
    const int warp  = tid >> 5;
    const int lane  = tid & 31;
    const int grp   = lane >> 2;              // 0..7
    const int tig   = lane & 3;               // 0..3
    const int wm    = warp >> 2;               // 0..1 -> 64 rows
    const int wn    = warp & 3;                // 0..3 -> 32 cols
    const int mbase = wm * 64;
    const int nbase = wn * 32;

    float acc[4][4][4];
    #pragma unroll
    for (int i = 0; i < 4; i++)
        #pragma unroll
        for (int j = 0; j < 4; j++)
            #pragma unroll
            for (int r = 0; r < 4; r++) acc[i][j][r] = 0.f;

    for (int k0 = 0; k0 < K; k0 += TBK) {
        // ---- fill A tile: 128x32 floats = 1024 float4; 4 per thread ----
        #pragma unroll
        for (int it = 0; it < 4; it++) {
            int linear = tid + it * 256;      // float4 index
            int row = linear >> 3;            // 8 float4 per 32-col row
            int k   = (linear & 7) << 2;
            float4 v = *(const float4*)(A + (long)(m0 + row) * lda + (k0 + k));
            __nv_bfloat16 hs[4], ls[4];
            float vv[4] = {v.x, v.y, v.z, v.w};
            #pragma unroll
            for (int q = 0; q < 4; q++) {
                hs[q] = __float2bfloat16(vv[q]);
                ls[q] = __float2bfloat16(vv[q] - __bfloat162float(hs[q]));
            }
            *(uint2*)&Ah[row][k] = *(uint2*)hs;
            *(uint2*)&Al[row][k] = *(uint2*)ls;
        }
        // ---- fill B tile: 128x32, guard rows >= N with zeros ----
        #pragma unroll
        for (int it = 0; it < 4; it++) {
            int linear = tid + it * 256;
            int row = linear >> 3;
            int k   = (linear & 7) << 2;
            float4 v = make_float4(0.f, 0.f, 0.f, 0.f);
            if (n0 + row < N)
                v = *(const float4*)(B + (long)(n0 + row) * ldb + (k0 + k));
            __nv_bfloat16 hs[4], ls[4];
            float vv[4] = {v.x, v.y, v.z, v.w};
            #pragma unroll
            for (int q = 0; q < 4; q++) {
                hs[q] = __float2bfloat16(vv[q]);
                ls[q] = __float2bfloat16(vv[q] - __bfloat162float(hs[q]));
            }
            *(uint2*)&Bh[row][k] = *(uint2*)hs;
            *(uint2*)&Bl[row][k] = *(uint2*)ls;
        }
        __syncthreads();

        #pragma unroll
        for (int kk = 0; kk < 2; kk++) {       // two k16 steps in BK=32
            const int kc = kk * 16;
            uint32_t ah[4][4], al[4][4], bhf[4][2], blf[4][2];
            #pragma unroll
            for (int mt = 0; mt < 4; mt++) {
                int r = mbase + mt * 16 + grp;
                ah[mt][0] = *(const uint32_t*)&Ah[r    ][kc + 2*tig    ];
                ah[mt][1] = *(const uint32_t*)&Ah[r + 8][kc + 2*tig    ];
                ah[mt][2] = *(const uint32_t*)&Ah[r    ][kc + 2*tig + 8];
                ah[mt][3] = *(const uint32_t*)&Ah[r + 8][kc + 2*tig + 8];
                al[mt][0] = *(const uint32_t*)&Al[r    ][kc + 2*tig    ];
                al[mt][1] = *(const uint32_t*)&Al[r + 8][kc + 2*tig    ];
                al[mt][2] = *(const uint32_t*)&Al[r    ][kc + 2*tig + 8];
                al[mt][3] = *(const uint32_t*)&Al[r + 8][kc + 2*tig + 8];
            }
            #pragma unroll
            for (int nt = 0; nt < 4; nt++) {
                int c = nbase + nt * 8 + grp;
                bhf[nt][0] = *(const uint32_t*)&Bh[c][kc + 2*tig    ];
                bhf[nt][1] = *(const uint32_t*)&Bh[c][kc + 2*tig + 8];
                blf[nt][0] = *(const uint32_t*)&Bl[c][kc + 2*tig    ];
                blf[nt][1] = *(const uint32_t*)&Bl[c][kc + 2*tig + 8];
            }
            #pragma unroll
            for (int mt = 0; mt < 4; mt++) {
                #pragma unroll
                for (int nt = 0; nt < 4; nt++) {
                    float* c4 = acc[mt][nt];
                    asm volatile(
                        "mma.sync.aligned.m16n8k16.row.col.f32.bf16.bf16.f32 "
                        "{%0,%1,%2,%3}, {%4,%5,%6,%7}, {%8,%9}, {%0,%1,%2,%3};\n"
                        : "+f"(c4[0]), "+f"(c4[1]), "+f"(c4[2]), "+f"(c4[3])
                        : "r"(ah[mt][0]), "r"(ah[mt][1]), "r"(ah[mt][2]), "r"(ah[mt][3]),
                          "r"(bhf[nt][0]), "r"(bhf[nt][1]));
                    asm volatile(
                        "mma.sync.aligned.m16n8k16.row.col.f32.bf16.bf16.f32 "
                        "{%0,%1,%2,%3}, {%4,%5,%6,%7}, {%8,%9}, {%0,%1,%2,%3};\n"
                        : "+f"(c4[0]), "+f"(c4[1]), "+f"(c4[2]), "+f"(c4[3])
                        : "r"(ah[mt][0]), "r"(ah[mt][1]), "r"(ah[mt][2]), "r"(ah[mt][3]),
                          "r"(blf[nt][0]), "r"(blf[nt][1]));
                    asm volatile(
                        "mma.sync.aligned.m16n8k16.row.col.f32.bf16.bf16.f32 "
                        "{%0,%1,%2,%3}, {%4,%5,%6,%7}, {%8,%9}, {%0,%1,%2,%3};\n"
                        : "+f"(c4[0]), "+f"(c4[1]), "+f"(c4[2]), "+f"(c4[3])
                        : "r"(al[mt][0]), "r"(al[mt][1]), "r"(al[mt][2]), "r"(al[mt][3]),
                          "r"(bhf[nt][0]), "r"(bhf[nt][1]));
                }
            }
        }
        __syncthreads();
    }

    // ---- epilogue ----
    #pragma unroll
    for (int mt = 0; mt < 4; mt++) {
        int r0 = m0 + mbase + mt * 16 + grp;
        #pragma unroll
        for (int nt = 0; nt < 4; nt++) {
            int c0 = n0 + nbase + nt * 8 + 2 * tig;
            #pragma unroll
            for (int rr = 0; rr < 2; rr++) {
                int m = r0 + rr * 8;
                #pragma unroll
                for (int cc = 0; cc < 2; cc++) {
                    int n = c0 + cc;
                    if (n < N) {
                        float v = acc[mt][nt][rr * 2 + cc];
                        if (bias) v += bias[n];
                        if (epi == 1) v = gelu_f(v);
                        long idx = (long)m * ldc + n;
                        if (epi == 2) v += C[idx];
                        C[idx] = v;
                    }
                }
            }
        }
    }
}

// =====================================================================
// SIMT GEMM (kept for P@V, NN layout): C = A(MxK) * B(KxN)
// =====================================================================
#define BM 64
#define BN 64
#define BK 16

__global__ void gemm_nn_kernel(const float* __restrict__ A, const float* __restrict__ B,
                               float* __restrict__ C,
                               int M, int N, int K, int lda, int ldb, int ldc,
                               long sAb, long sAh, long sBb, long sBh, long sCb, long sCh,
                               int nh)
{
    int z  = blockIdx.z;
    int bb = z / nh, hh = z % nh;
    A += (long)bb * sAb + (long)hh * sAh;
    B += (long)bb * sBb + (long)hh * sBh;
    C += (long)bb * sCb + (long)hh * sCh;

    const int m0 = blockIdx.y * BM;
    const int n0 = blockIdx.x * BN;

    __shared__ float As[BK][BM];
    __shared__ float Bs[BK][BN];

    const int tid = threadIdx.x;
    const int tx  = tid & 15;
    const int ty  = tid >> 4;

    float acc[4][4] = {};

    for (int k0 = 0; k0 < K; k0 += BK) {
        {
            int m  = tid >> 2;
            int kq = (tid & 3) * 4;
            float4 v = *(const float4*)(A + (long)(m0 + m) * lda + (k0 + kq));
            As[kq + 0][m] = v.x; As[kq + 1][m] = v.y;
            As[kq + 2][m] = v.z; As[kq + 3][m] = v.w;
        }
        {
            int n = (tid & 15) * 4;
            int k = tid >> 4;
            const float* brow = B + (long)(k0 + k) * ldb;
            float4 v;
            v.x = (n0 + n     < N) ? brow[n0 + n    ] : 0.f;
            v.y = (n0 + n + 1 < N) ? brow[n0 + n + 1] : 0.f;
            v.z = (n0 + n + 2 < N) ? brow[n0 + n + 2] : 0.f;
            v.w = (n0 + n + 3 < N) ? brow[n0 + n + 3] : 0.f;
            *(float4*)&Bs[k][n] = v;
        }
        __syncthreads();

        #pragma unroll
        for (int kk = 0; kk < BK; kk++) {
            float4 a4 = *(const float4*)&As[kk][ty * 4];
            float4 b4 = *(const float4*)&Bs[kk][tx * 4];
            float a[4] = {a4.x, a4.y, a4.z, a4.w};
            float b[4] = {b4.x, b4.y, b4.z, b4.w};
            #pragma unroll
            for (int i = 0; i < 4; i++)
                #pragma unroll
                for (int j = 0; j < 4; j++)
                    acc[i][j] += a[i] * b[j];
        }
        __syncthreads();
    }

    #pragma unroll
    for (int i = 0; i < 4; i++) {
        int m = m0 + ty * 4 + i;
        #pragma unroll
        for (int j = 0; j < 4; j++) {
            int n = n0 + tx * 4 + j;
            if (n < N) C[(long)m * ldc + n] = acc[i][j];
        }
    }
}

// =====================================================================
// im2col for patch embed
// =====================================================================
__global__ void im2col_kernel(const float* __restrict__ x, float* __restrict__ col)
{
    long idx = (long)blockIdx.x * blockDim.x + threadIdx.x;
    if (idx >= (long)MROWS * CDIM) return;
    int k = (int)(idx % CDIM);
    int m = (int)(idx / CDIM);
    int b  = m >> 10;
    int n  = m & 1023;
    int hp = n >> 5, wp = n & 31;
    int ci = k >> 8;
    int r  = k & 255;
    int ky = r >> 4, kx = r & 15;
    long src = (((long)(b * 3 + ci) * IMG) + hp * PS + ky) * IMG + wp * PS + kx;
    col[idx] = x[src];
}

// =====================================================================
// LayerNorm: one block (256 thr) per token row of 768
// =====================================================================
__global__ void layernorm_kernel(const float* __restrict__ in, float* __restrict__ out,
                                 const float* __restrict__ s, const float* __restrict__ b)
{
    __shared__ float red[8];
    const long row = blockIdx.x;
    const float* r = in + row * CDIM;
    float* o = out + row * CDIM;
    int tid = threadIdx.x, lane = tid & 31, w = tid >> 5;

    float v[3];
    float sum = 0.f;
    #pragma unroll
    for (int j = 0; j < 3; j++) { v[j] = r[tid + j * 256]; sum += v[j]; }
    #pragma unroll
    for (int off = 16; off; off >>= 1) sum += __shfl_xor_sync(~0u, sum, off);
    if (lane == 0) red[w] = sum;
    __syncthreads();
    if (w == 0) {
        float t = (lane < 8) ? red[lane] : 0.f;
        #pragma unroll
        for (int off = 4; off; off >>= 1) t += __shfl_xor_sync(~0u, t, off);
        if (lane == 0) red[0] = t;
    }
    __syncthreads();
    float mu = red[0] * (1.f / CDIM);
    __syncthreads();

    float sq = 0.f;
    #pragma unroll
    for (int j = 0; j < 3; j++) { float d = v[j] - mu; sq += d * d; }
    #pragma unroll
    for (int off = 16; off; off >>= 1) sq += __shfl_xor_sync(~0u, sq, off);
    if (lane == 0) red[w] = sq;
    __syncthreads();
    if (w == 0) {
        float t = (lane < 8) ? red[lane] : 0.f;
        #pragma unroll
        for (int off = 4; off; off >>= 1) t += __shfl_xor_sync(~0u, t, off);
        if (lane == 0) red[0] = t;
    }
    __syncthreads();
    float rstd = rsqrtf(red[0] * (1.f / CDIM) + EPS_F);

    #pragma unroll
    for (int j = 0; j < 3; j++) {
        int c = tid + j * 256;
        o[c] = (v[j] - mu) * rstd * s[c] + b[c];
    }
}

// =====================================================================
// Row softmax over 1024 keys, with scale (full attention path, in-place)
// =====================================================================
__global__ void softmax_kernel(float* __restrict__ sc)
{
    __shared__ float red[8];
    float* r = sc + (long)blockIdx.x * NTOK;
    int tid = threadIdx.x, lane = tid & 31, w = tid >> 5;

    float v[4], mx = -1e30f;
    #pragma unroll
    for (int j = 0; j < 4; j++) { v[j] = r[tid + j * 256] * SCALE_F; mx = fmaxf(mx, v[j]); }
    #pragma unroll
    for (int off = 16; off; off >>= 1) mx = fmaxf(mx, __shfl_xor_sync(~0u, mx, off));
    if (lane == 0) red[w] = mx;
    __syncthreads();
    if (w == 0) {
        float t = (lane < 8) ? red[lane] : -1e30f;
        #pragma unroll
        for (int off = 4; off; off >>= 1) t = fmaxf(t, __shfl_xor_sync(~0u, t, off));
        if (lane == 0) red[0] = t;
    }
    __syncthreads();
    mx = red[0];
    __syncthreads();

    float sum = 0.f;
    #pragma unroll
    for (int j = 0; j < 4; j++) { v[j] = expf(v[j] - mx); sum += v[j]; }
    #pragma unroll
    for (int off = 16; off; off >>= 1) sum += __shfl_xor_sync(~0u, sum, off);
    if (lane == 0) red[w] = sum;
    __syncthreads();
    if (w == 0) {
        float t = (lane < 8) ? red[lane] : 0.f;
        #pragma unroll
        for (int off = 4; off; off >>= 1) t += __shfl_xor_sync(~0u, t, off);
        if (lane == 0) red[0] = t;
    }
    __syncthreads();
    float inv = 1.f / red[0];
    #pragma unroll
    for (int j = 0; j < 4; j++) r[tid + j * 256] = v[j] * inv;
}

// =====================================================================
// Fused deformable attention: one warp per (b, h, n).
// =====================================================================
__global__ void deform_attn_kernel(const float* __restrict__ qkv,
                                   const float* __restrict__ offs,
                                   float* __restrict__ out)
{
    int gwarp = (blockIdx.x * blockDim.x + threadIdx.x) >> 5;
    int lane  = threadIdx.x & 31;
    if (gwarp >= BB * NHEADS * NTOK) return;
    int n  = gwarp & (NTOK - 1);
    int bh = gwarp >> 10;
    int h  = bh % NHEADS;
    int b  = bh / NHEADS;
    int hp = n >> 5, wp = n & 31;

    const float* qrow = qkv + ((long)(b * NTOK + n)) * (3 * CDIM) + h * HEADD;
    float q0 = qrow[lane], q1 = qrow[lane + 32];

    const float* offrow = offs + ((long)(b * NTOK + n)) * 96 + h * NPTS * 2;

    float att[NPTS], sv0[NPTS], sv1[NPTS];

    #pragma unroll
    for (int p = 0; p < NPTS; p++) {
        float ox = offrow[p * 2 + 0];
        float oy = offrow[p * 2 + 1];
        float gx = (wp + 0.5f) * (1.f / HP) + ox * (1.f / HP);
        float gy = (hp + 0.5f) * (1.f / HP) + oy * (1.f / HP);
        float lx = 2.f * gx - 1.f;
        float ly = 2.f * gy - 1.f;
        float px = (lx + 1.f) * (HP * 0.5f) - 0.5f;
        float py = (ly + 1.f) * (HP * 0.5f) - 0.5f;
        float x0f = floorf(px), y0f = floorf(py);
        float wx = px - x0f, wy = py - y0f;
        int x0 = (int)x0f, y0 = (int)y0f;
        float cw[4] = { (1.f - wx) * (1.f - wy), wx * (1.f - wy),
                        (1.f - wx) * wy,         wx * wy };

        float k0 = 0.f, k1 = 0.f, v0 = 0.f, v1 = 0.f;
        #pragma unroll
        for (int c = 0; c < 4; c++) {
            int yi = y0 + (c >> 1);
            int xi = x0 + (c & 1);
            if (yi >= 0 && yi < HP && xi >= 0 && xi < HP) {
                const float* kr = qkv + ((long)(b * NTOK + yi * HP + xi)) * (3 * CDIM)
                                      + CDIM + h * HEADD;
                const float* vr = kr + CDIM;
                float wc = cw[c];
                k0 += wc * kr[lane];      k1 += wc * kr[lane + 32];
                v0 += wc * vr[lane];      v1 += wc * vr[lane + 32];
            }
        }
        sv0[p] = v0; sv1[p] = v1;
        float d = q0 * k0 + q1 * k1;
        #pragma unroll
        for (int off = 16; off; off >>= 1) d += __shfl_xor_sync(~0u, d, off);
        att[p] = d * SCALE_F;
    }

    float mx = fmaxf(fmaxf(att[0], att[1]), fmaxf(att[2], att[3]));
    float e[NPTS], sum = 0.f;
    #pragma unroll
    for (int p = 0; p < NPTS; p++) { e[p] = expf(att[p] - mx); sum += e[p]; }
    float inv = 1.f / sum;

    float o0 = 0.f, o1 = 0.f;
    #pragma unroll
    for (int p = 0; p < NPTS; p++) {
        float a = e[p] * inv;
        o0 += a * sv0[p];
        o1 += a * sv1[p];
    }
    float* orow = out + ((long)(b * NTOK + n)) * CDIM + h * HEADD;
    orow[lane]      = o0;
    orow[lane + 32] = o1;
}

// =====================================================================
// Output transpose: (B,N,C) -> (B,C,Hp,Wp)
// =====================================================================
__global__ void out_transpose_kernel(const float* __restrict__ x, float* __restrict__ out)
{
    long idx = (long)blockIdx.x * blockDim.x + threadIdx.x;
    if (idx >= (long)MROWS * CDIM) return;
    int n = (int)(idx % NTOK);
    int c = (int)((idx / NTOK) % CDIM);
    int b = (int)(idx / ((long)NTOK * CDIM));
    out[idx] = x[((long)(b * NTOK + n)) * CDIM + c];
}

// =====================================================================
// Host launcher
// =====================================================================
extern "C" void kernel_launch(void* const* d_in, const int* in_sizes, int n_in,
                              void* d_out, int out_size)
{
    const float* x       = (const float*)d_in[0];
    const float* patch_w = (const float*)d_in[1];
    const float* patch_b = (const float*)d_in[2];
    const float* ln1_s   = (const float*)d_in[3];
    const float* ln1_b   = (const float*)d_in[4];
    const float* qkv_w   = (const float*)d_in[5];
    const float* offs_w  = (const float*)d_in[6];
    const float* offs_b  = (const float*)d_in[7];
    const float* proj_w  = (const float*)d_in[8];
    const float* proj_b  = (const float*)d_in[9];
    const float* ln2_s   = (const float*)d_in[10];
    const float* ln2_b   = (const float*)d_in[11];
    const float* fc1_w   = (const float*)d_in[12];
    const float* fc1_b   = (const float*)d_in[13];
    const float* fc2_w   = (const float*)d_in[14];
    const float* fc2_b   = (const float*)d_in[15];

    float *gx, *gh, *gqkv, *gcol, *goffs, *gao, *gsc, *gmlp;
    cudaGetSymbolAddress((void**)&gx,   g_x);
    cudaGetSymbolAddress((void**)&gh,   g_h);
    cudaGetSymbolAddress((void**)&gqkv, g_qkv);
    cudaGetSymbolAddress((void**)&gcol, g_col);
    cudaGetSymbolAddress((void**)&goffs,g_offs);
    cudaGetSymbolAddress((void**)&gao,  g_ao);
    cudaGetSymbolAddress((void**)&gsc,  g_sc);
    cudaGetSymbolAddress((void**)&gmlp, g_mlp);

    const int M = MROWS; // 2048

    // ---- patch embed: im2col + GEMM ----
    im2col_kernel<<<(M * CDIM + 255) / 256, 256>>>(x, gcol);
    mma_gemm_kernel<<<dim3(CDIM / TBN, M / TBM, 1), 256>>>(
        gcol, patch_w, gx, patch_b,
        M, CDIM, CDIM, CDIM, CDIM, CDIM,
        0, 0, 0, 0, 0, 0, 1, 0);

    for (int i = 0; i < 6; i++) {
        // LN1
        layernorm_kernel<<<M, 256>>>(gx, gh, ln1_s + i * CDIM, ln1_b + i * CDIM);
        // QKV (no bias)
        mma_gemm_kernel<<<dim3(2304 / TBN, M / TBM, 1), 256>>>(
            gh, qkv_w + (long)i * 2304 * CDIM, gqkv, nullptr,
            M, 2304, CDIM, CDIM, CDIM, 2304,
            0, 0, 0, 0, 0, 0, 1, 0);

        bool sample = ((i + 1) % 3) != 0;
        if (sample) {
            // offsets = q @ offs_w^T + offs_b
            mma_gemm_kernel<<<dim3(1, M / TBM, 1), 256>>>(
                gqkv, offs_w + (long)i * 96 * CDIM, goffs, offs_b + i * 96,
                M, 96, CDIM, 3 * CDIM, CDIM, 96,
                0, 0, 0, 0, 0, 0, 1, 0);
            deform_attn_kernel<<<(BB * NHEADS * NTOK * 32) / 256, 256>>>(gqkv, goffs, gao);
        } else {
            // scores = q @ k^T (batched over B*NH); scale applied in softmax
            mma_gemm_kernel<<<dim3(NTOK / TBN, NTOK / TBM, BB * NHEADS), 256>>>(
                gqkv, gqkv + CDIM, gsc, nullptr,
                NTOK, NTOK, HEADD, 3 * CDIM, 3 * CDIM, NTOK,
                (long)NTOK * 3 * CDIM, HEADD,
                (long)NTOK * 3 * CDIM, HEADD,
                (long)NHEADS * NTOK * NTOK, (long)NTOK * NTOK,
                NHEADS, 0);
            softmax_kernel<<<BB * NHEADS * NTOK, 256>>>(gsc);
            // out = P @ V   (NN, SIMT)
            gemm_nn_kernel<<<dim3(1, NTOK / BM, BB * NHEADS), 256>>>(
                gsc, gqkv + 2 * CDIM, gao,
                NTOK, HEADD, NTOK, NTOK, 3 * CDIM, CDIM,
                (long)NHEADS * NTOK * NTOK, (long)NTOK * NTOK,
                (long)NTOK * 3 * CDIM, HEADD,
                (long)NTOK * CDIM, HEADD,
                NHEADS);
        }

        // proj + residual into x
        mma_gemm_kernel<<<dim3(CDIM / TBN, M / TBM, 1), 256>>>(
            gao, proj_w + (long)i * CDIM * CDIM, gx, proj_b + i * CDIM,
            M, CDIM, CDIM, CDIM, CDIM, CDIM,
            0, 0, 0, 0, 0, 0, 1, 2);

        // LN2
        layernorm_kernel<<<M, 256>>>(gx, gh, ln2_s + i * CDIM, ln2_b + i * CDIM);
        // fc1 + gelu
        mma_gemm_kernel<<<dim3(3072 / TBN, M / TBM, 1), 256>>>(
            gh, fc1_w + (long)i * 3072 * CDIM, gmlp, fc1_b + i * 3072,
            M, 3072, CDIM, CDIM, CDIM, 3072,
            0, 0, 0, 0, 0, 0, 1, 1);
        // fc2 + residual into x
        mma_gemm_kernel<<<dim3(CDIM / TBN, M / TBM, 1), 256>>>(
            gmlp, fc2_w + (long)i * CDIM * 3072, gx, fc2_b + i * CDIM,
            M, CDIM, 3072, 3072, 3072, CDIM,
            0, 0, 0, 0, 0, 0, 1, 2);
    }

    out_transpose_kernel<<<(M * CDIM + 255) / 256, 256>>>(gx, (float*)d_out);
}

// round 4
// speedup vs baseline: 1.9292x; 1.0077x over previous
#include <cuda_runtime.h>
#include <cuda_bf16.h>
#include <math.h>
#include <cstdint>
#include <cstddef>

// ---------------- problem constants ----------------
#define BB       2
#define IMG      512
#define PS       16
#define HP       32
#define NTOK     1024
#define CDIM     768
#define NHEADS   12
#define HEADD    64
#define NPTS     4
#define SCALE_F  0.125f
#define EPS_F    1e-6f
#define MROWS    (BB*NTOK)   // 2048

typedef __nv_bfloat16 bf16;

// ---------------- device scratch ----------------
__device__ float g_x   [MROWS*CDIM];
__device__ float g_qkv [MROWS*3*CDIM];
__device__ float g_offs[MROWS*96];
__device__ float g_sc  [(size_t)BB*NHEADS*NTOK*NTOK];

__device__ bf16 g_hh  [MROWS*CDIM],      g_hl  [MROWS*CDIM];
__device__ bf16 g_colh[MROWS*CDIM],      g_coll[MROWS*CDIM];
__device__ bf16 g_qkvh[MROWS*3*CDIM],    g_qkvl[MROWS*3*CDIM];
__device__ bf16 g_aoh [MROWS*CDIM],      g_aol [MROWS*CDIM];
__device__ bf16 g_sch [(size_t)BB*NHEADS*NTOK*NTOK];
__device__ bf16 g_scl [(size_t)BB*NHEADS*NTOK*NTOK];
__device__ bf16 g_mlph[MROWS*4*CDIM],    g_mlpl[MROWS*4*CDIM];
__device__ bf16 g_vth [BB*NHEADS*HEADD*NTOK], g_vtl[BB*NHEADS*HEADD*NTOK];

// weight bf16 hi/lo (converted once per launch)
__device__ bf16 g_pwh[CDIM*CDIM],        g_pwl[CDIM*CDIM];
__device__ bf16 g_qwh[6*3*CDIM*CDIM],    g_qwl[6*3*CDIM*CDIM];
__device__ bf16 g_owh[6*96*CDIM],        g_owl[6*96*CDIM];
__device__ bf16 g_jwh[6*CDIM*CDIM],      g_jwl[6*CDIM*CDIM];
__device__ bf16 g_f1h[6*4*CDIM*CDIM],    g_f1l[6*4*CDIM*CDIM];
__device__ bf16 g_f2h[6*4*CDIM*CDIM],    g_f2l[6*4*CDIM*CDIM];

// ---------------- helpers ----------------
__device__ __forceinline__ float gelu_f(float v) {
    return 0.5f * v * (1.0f + erff(v * 0.7071067811865476f));
}
__device__ __forceinline__ void split_pair(float v, bf16& hi, bf16& lo) {
    hi = __float2bfloat16(v);
    lo = __float2bfloat16(v - __bfloat162float(hi));
}
__device__ __forceinline__ uint32_t smem_u32(const void* p) {
    return (uint32_t)__cvta_generic_to_shared(p);
}
__device__ __forceinline__ void cp_async16(uint32_t dst, const void* src, bool pred) {
    int sz = pred ? 16 : 0;
    asm volatile("cp.async.cg.shared.global [%0], [%1], 16, %2;\n"
                 :: "r"(dst), "l"(src), "r"(sz));
}

// =====================================================================
// bf16 hi/lo 3-product tensor-core GEMM with cp.async double buffering.
//   C = epi( A(MxK) * B(NxK)^T + bias )
// A,B given as bf16 hi/lo pairs, row-major. Outputs: optional f32 Cf,
// optional bf16 pair (Chi,Clo). epi: 0 none, 1 gelu, 2 residual (+=Cf).
// Requires M%128==0, K%32==0. N guarded. 256 threads.
// =====================================================================
#define TBM 128
#define TBN 128
#define TBK 32
#define SPAD 40
#define STG_ARR 5120            // bf16 per array (128*40)

extern __shared__ bf16 smem_dyn[];   // [2][4][STG_ARR] = 80KB

__global__ __launch_bounds__(256)
void mma_gemm_kernel(const bf16* __restrict__ Ah_g, const bf16* __restrict__ Al_g,
                     const bf16* __restrict__ Bh_g, const bf16* __restrict__ Bl_g,
                     float* Cf, bf16* Chi, bf16* Clo,
                     const float* __restrict__ bias,
                     int M, int N, int K, int lda, int ldb, int ldc,
                     long sAb, long sAh2, long sBb, long sBh2, long sCb, long sCh2,
                     int nh, int epi)
{
    int z  = blockIdx.z;
    int bb = z / nh, hh = z % nh;
    long aoff = (long)bb * sAb + (long)hh * sAh2;
    long boff = (long)bb * sBb + (long)hh * sBh2;
    long coff = (long)bb * sCb + (long)hh * sCh2;
    Ah_g += aoff; Al_g += aoff; Bh_g += boff; Bl_g += boff;
    if (Cf)  Cf  += coff;
    if (Chi) { Chi += coff; Clo += coff; }

    const int m0 = blockIdx.y * TBM;
    const int n0 = blockIdx.x * TBN;

    const int tid  = threadIdx.x;
    const int warp = tid >> 5;
    const int lane = tid & 31;
    const int grp  = lane >> 2;
    const int tig  = lane & 3;
    const int mbase = (warp >> 2) * 64;
    const int nbase = (warp & 3) * 32;

    bf16* S = smem_dyn;

    float acc[4][4][4];
    #pragma unroll
    for (int i = 0; i < 4; i++)
        #pragma unroll
        for (int j = 0; j < 4; j++)
            #pragma unroll
            for (int r = 0; r < 4; r++) acc[i][j][r] = 0.f;

    const int KT = K / TBK;

    auto load_stage = [&](int s, int kt) {
        int k0 = kt * TBK;
        #pragma unroll
        for (int i = 0; i < 8; i++) {
            int linear = tid + i * 256;
            int arr = linear >> 9;
            int rem = linear & 511;
            int row = rem >> 2;
            int ch  = rem & 3;
            uint32_t dst = smem_u32(&S[(s * 4 + arr) * STG_ARR + row * SPAD + ch * 8]);
            if (arr == 0) {
                cp_async16(dst, Ah_g + (long)(m0 + row) * lda + k0 + ch * 8, true);
            } else if (arr == 1) {
                cp_async16(dst, Al_g + (long)(m0 + row) * lda + k0 + ch * 8, true);
            } else {
                int r = n0 + row;
                bool pred = r < N;
                int rr = pred ? r : 0;
                const bf16* src = ((arr == 2) ? Bh_g : Bl_g) + (long)rr * ldb + k0 + ch * 8;
                cp_async16(dst, src, pred);
            }
        }
        asm volatile("cp.async.commit_group;\n");
    };

    load_stage(0, 0);

    for (int kt = 0; kt < KT; kt++) {
        int cur = kt & 1;
        if (kt + 1 < KT) {
            load_stage(cur ^ 1, kt + 1);
            asm volatile("cp.async.wait_group 1;\n");
        } else {
            asm volatile("cp.async.wait_group 0;\n");
        }
        __syncthreads();

        const bf16* sAh = S + (cur * 4 + 0) * STG_ARR;
        const bf16* sAl = S + (cur * 4 + 1) * STG_ARR;
        const bf16* sBh = S + (cur * 4 + 2) * STG_ARR;
        const bf16* sBl = S + (cur * 4 + 3) * STG_ARR;

        #pragma unroll
        for (int kk = 0; kk < 2; kk++) {
            const int kc = kk * 16;
            uint32_t ah[4][4], al[4][4], bhf[4][2], blf[4][2];
            #pragma unroll
            for (int mt = 0; mt < 4; mt++) {
                int r = mbase + mt * 16 + grp;
                ah[mt][0] = *(const uint32_t*)&sAh[(r    ) * SPAD + kc + 2*tig    ];
                ah[mt][1] = *(const uint32_t*)&sAh[(r + 8) * SPAD + kc + 2*tig    ];
                ah[mt][2] = *(const uint32_t*)&sAh[(r    ) * SPAD + kc + 2*tig + 8];
                ah[mt][3] = *(const uint32_t*)&sAh[(r + 8) * SPAD + kc + 2*tig + 8];
                al[mt][0] = *(const uint32_t*)&sAl[(r    ) * SPAD + kc + 2*tig    ];
                al[mt][1] = *(const uint32_t*)&sAl[(r + 8) * SPAD + kc + 2*tig    ];
                al[mt][2] = *(const uint32_t*)&sAl[(r    ) * SPAD + kc + 2*tig + 8];
                al[mt][3] = *(const uint32_t*)&sAl[(r + 8) * SPAD + kc + 2*tig + 8];
            }
            #pragma unroll
            for (int nt = 0; nt < 4; nt++) {
                int c = nbase + nt * 8 + grp;
                bhf[nt][0] = *(const uint32_t*)&sBh[c * SPAD + kc + 2*tig    ];
                bhf[nt][1] = *(const uint32_t*)&sBh[c * SPAD + kc + 2*tig + 8];
                blf[nt][0] = *(const uint32_t*)&sBl[c * SPAD + kc + 2*tig    ];
                blf[nt][1] = *(const uint32_t*)&sBl[c * SPAD + kc + 2*tig + 8];
            }
            #pragma unroll
            for (int mt = 0; mt < 4; mt++) {
                #pragma unroll
                for (int nt = 0; nt < 4; nt++) {
                    float* c4 = acc[mt][nt];
                    asm volatile(
                        "mma.sync.aligned.m16n8k16.row.col.f32.bf16.bf16.f32 "
                        "{%0,%1,%2,%3}, {%4,%5,%6,%7}, {%8,%9}, {%0,%1,%2,%3};\n"
                        : "+f"(c4[0]), "+f"(c4[1]), "+f"(c4[2]), "+f"(c4[3])
                        : "r"(ah[mt][0]), "r"(ah[mt][1]), "r"(ah[mt][2]), "r"(ah[mt][3]),
                          "r"(bhf[nt][0]), "r"(bhf[nt][1]));
                    asm volatile(
                        "mma.sync.aligned.m16n8k16.row.col.f32.bf16.bf16.f32 "
                        "{%0,%1,%2,%3}, {%4,%5,%6,%7}, {%8,%9}, {%0,%1,%2,%3};\n"
                        : "+f"(c4[0]), "+f"(c4[1]), "+f"(c4[2]), "+f"(c4[3])
                        : "r"(ah[mt][0]), "r"(ah[mt][1]), "r"(ah[mt][2]), "r"(ah[mt][3]),
                          "r"(blf[nt][0]), "r"(blf[nt][1]));
                    asm volatile(
                        "mma.sync.aligned.m16n8k16.row.col.f32.bf16.bf16.f32 "
                        "{%0,%1,%2,%3}, {%4,%5,%6,%7}, {%8,%9}, {%0,%1,%2,%3};\n"
                        : "+f"(c4[0]), "+f"(c4[1]), "+f"(c4[2]), "+f"(c4[3])
                        : "r"(al[mt][0]), "r"(al[mt][1]), "r"(al[mt][2]), "r"(al[mt][3]),
                          "r"(bhf[nt][0]), "r"(bhf[nt][1]));
                }
            }
        }
        __syncthreads();
    }

    // ---- epilogue ----
    #pragma unroll
    for (int mt = 0; mt < 4; mt++) {
        int r0 = m0 + mbase + mt * 16 + grp;
        #pragma unroll
        for (int nt = 0; nt < 4; nt++) {
            int c0 = n0 + nbase + nt * 8 + 2 * tig;
            #pragma unroll
            for (int rr = 0; rr < 2; rr++) {
                int m = r0 + rr * 8;
                #pragma unroll
                for (int cc = 0; cc < 2; cc++) {
                    int n = c0 + cc;
                    if (n < N) {
                        float v = acc[mt][nt][rr * 2 + cc];
                        if (bias) v += bias[n];
                        if (epi == 1) v = gelu_f(v);
                        long idx = (long)m * ldc + n;
                        if (epi == 2) v += Cf[idx];
                        if (Cf) Cf[idx] = v;
                        if (Chi) { bf16 h, l; split_pair(v, h, l); Chi[idx] = h; Clo[idx] = l; }
                    }
                }
            }
        }
    }
}

// =====================================================================
// f32 -> bf16 hi/lo pair conversion (weights, once per launch)
// =====================================================================
__global__ void cvt_pair_kernel(const float* __restrict__ in,
                                bf16* __restrict__ hi, bf16* __restrict__ lo, long n)
{
    long i = (long)blockIdx.x * blockDim.x + threadIdx.x;
    if (i >= n) return;
    bf16 h, l; split_pair(in[i], h, l);
    hi[i] = h; lo[i] = l;
}

// =====================================================================
// im2col producing bf16 pairs
// =====================================================================
__global__ void im2col_kernel(const float* __restrict__ x,
                              bf16* __restrict__ ch, bf16* __restrict__ cl)
{
    long idx = (long)blockIdx.x * blockDim.x + threadIdx.x;
    if (idx >= (long)MROWS * CDIM) return;
    int k = (int)(idx % CDIM);
    int m = (int)(idx / CDIM);
    int b  = m >> 10;
    int n  = m & 1023;
    int hp = n >> 5, wp = n & 31;
    int ci = k >> 8;
    int r  = k & 255;
    int ky = r >> 4, kx = r & 15;
    long src = (((long)(b * 3 + ci) * IMG) + hp * PS + ky) * IMG + wp * PS + kx;
    bf16 h, l; split_pair(x[src], h, l);
    ch[idx] = h; cl[idx] = l;
}

// =====================================================================
// LayerNorm producing bf16 pairs
// =====================================================================
__global__ void layernorm_kernel(const float* __restrict__ in,
                                 bf16* __restrict__ oh, bf16* __restrict__ ol,
                                 const float* __restrict__ s, const float* __restrict__ b)
{
    __shared__ float red[8];
    const long row = blockIdx.x;
    const float* r = in + row * CDIM;
    int tid = threadIdx.x, lane = tid & 31, w = tid >> 5;

    float v[3];
    float sum = 0.f;
    #pragma unroll
    for (int j = 0; j < 3; j++) { v[j] = r[tid + j * 256]; sum += v[j]; }
    #pragma unroll
    for (int off = 16; off; off >>= 1) sum += __shfl_xor_sync(~0u, sum, off);
    if (lane == 0) red[w] = sum;
    __syncthreads();
    if (w == 0) {
        float t = (lane < 8) ? red[lane] : 0.f;
        #pragma unroll
        for (int off = 4; off; off >>= 1) t += __shfl_xor_sync(~0u, t, off);
        if (lane == 0) red[0] = t;
    }
    __syncthreads();
    float mu = red[0] * (1.f / CDIM);
    __syncthreads();

    float sq = 0.f;
    #pragma unroll
    for (int j = 0; j < 3; j++) { float d = v[j] - mu; sq += d * d; }
    #pragma unroll
    for (int off = 16; off; off >>= 1) sq += __shfl_xor_sync(~0u, sq, off);
    if (lane == 0) red[w] = sq;
    __syncthreads();
    if (w == 0) {
        float t = (lane < 8) ? red[lane] : 0.f;
        #pragma unroll
        for (int off = 4; off; off >>= 1) t += __shfl_xor_sync(~0u, t, off);
        if (lane == 0) red[0] = t;
    }
    __syncthreads();
    float rstd = rsqrtf(red[0] * (1.f / CDIM) + EPS_F);

    #pragma unroll
    for (int j = 0; j < 3; j++) {
        int c = tid + j * 256;
        float o = (v[j] - mu) * rstd * s[c] + b[c];
        bf16 h, l; split_pair(o, h, l);
        oh[row * CDIM + c] = h; ol[row * CDIM + c] = l;
    }
}

// =====================================================================
// Row softmax over 1024 keys, scale fused, writes bf16 pairs
// =====================================================================
__global__ void softmax_kernel(const float* __restrict__ sc,
                               bf16* __restrict__ ph, bf16* __restrict__ pl)
{
    __shared__ float red[8];
    const float* r = sc + (long)blockIdx.x * NTOK;
    int tid = threadIdx.x, lane = tid & 31, w = tid >> 5;

    float v[4], mx = -1e30f;
    #pragma unroll
    for (int j = 0; j < 4; j++) { v[j] = r[tid + j * 256] * SCALE_F; mx = fmaxf(mx, v[j]); }
    #pragma unroll
    for (int off = 16; off; off >>= 1) mx = fmaxf(mx, __shfl_xor_sync(~0u, mx, off));
    if (lane == 0) red[w] = mx;
    __syncthreads();
    if (w == 0) {
        float t = (lane < 8) ? red[lane] : -1e30f;
        #pragma unroll
        for (int off = 4; off; off >>= 1) t = fmaxf(t, __shfl_xor_sync(~0u, t, off));
        if (lane == 0) red[0] = t;
    }
    __syncthreads();
    mx = red[0];
    __syncthreads();

    float sum = 0.f;
    #pragma unroll
    for (int j = 0; j < 4; j++) { v[j] = expf(v[j] - mx); sum += v[j]; }
    #pragma unroll
    for (int off = 16; off; off >>= 1) sum += __shfl_xor_sync(~0u, sum, off);
    if (lane == 0) red[w] = sum;
    __syncthreads();
    if (w == 0) {
        float t = (lane < 8) ? red[lane] : 0.f;
        #pragma unroll
        for (int off = 4; off; off >>= 1) t += __shfl_xor_sync(~0u, t, off);
        if (lane == 0) red[0] = t;
    }
    __syncthreads();
    float inv = 1.f / red[0];
    #pragma unroll
    for (int j = 0; j < 4; j++) {
        float p = v[j] * inv;
        bf16 h, l; split_pair(p, h, l);
        long idx = (long)blockIdx.x * NTOK + tid + j * 256;
        ph[idx] = h; pl[idx] = l;
    }
}

// =====================================================================
// V transpose to per-head (d, t) layout, bf16 pairs
// vT[(b*NH+h)*64 + d][t] = qkv[(b*NTOK+t)*2304 + 1536 + h*64 + d]
// =====================================================================
__global__ void vtrans_kernel(const float* __restrict__ qkv,
                              bf16* __restrict__ vh, bf16* __restrict__ vl)
{
    long idx = (long)blockIdx.x * blockDim.x + threadIdx.x;
    if (idx >= (long)BB * NHEADS * HEADD * NTOK) return;
    int t  = (int)(idx & 1023);
    long r = idx >> 10;
    int d  = (int)(r & 63);
    int bh = (int)(r >> 6);
    int h  = bh % NHEADS;
    int b  = bh / NHEADS;
    float v = qkv[((long)(b * NTOK + t)) * (3 * CDIM) + 2 * CDIM + h * HEADD + d];
    bf16 hi, lo; split_pair(v, hi, lo);
    vh[idx] = hi; vl[idx] = lo;
}

// =====================================================================
// Fused deformable attention: one warp per (b, h, n). Writes bf16 pairs.
// =====================================================================
__global__ void deform_attn_kernel(const float* __restrict__ qkv,
                                   const float* __restrict__ offs,
                                   bf16* __restrict__ oh, bf16* __restrict__ ol)
{
    int gwarp = (blockIdx.x * blockDim.x + threadIdx.x) >> 5;
    int lane  = threadIdx.x & 31;
    if (gwarp >= BB * NHEADS * NTOK) return;
    int n  = gwarp & (NTOK - 1);
    int bh = gwarp >> 10;
    int h  = bh % NHEADS;
    int b  = bh / NHEADS;
    int hp = n >> 5, wp = n & 31;

    const float* qrow = qkv + ((long)(b * NTOK + n)) * (3 * CDIM) + h * HEADD;
    float q0 = qrow[lane], q1 = qrow[lane + 32];

    const float* offrow = offs + ((long)(b * NTOK + n)) * 96 + h * NPTS * 2;

    float att[NPTS], sv0[NPTS], sv1[NPTS];

    #pragma unroll
    for (int p = 0; p < NPTS; p++) {
        float ox = offrow[p * 2 + 0];
        float oy = offrow[p * 2 + 1];
        float gx = (wp + 0.5f) * (1.f / HP) + ox * (1.f / HP);
        float gy = (hp + 0.5f) * (1.f / HP) + oy * (1.f / HP);
        float px = (2.f * gx - 1.f + 1.f) * (HP * 0.5f) - 0.5f;
        float py = (2.f * gy - 1.f + 1.f) * (HP * 0.5f) - 0.5f;
        float x0f = floorf(px), y0f = floorf(py);
        float wx = px - x0f, wy = py - y0f;
        int x0 = (int)x0f, y0 = (int)y0f;
        float cw[4] = { (1.f - wx) * (1.f - wy), wx * (1.f - wy),
                        (1.f - wx) * wy,         wx * wy };

        float k0 = 0.f, k1 = 0.f, v0 = 0.f, v1 = 0.f;
        #pragma unroll
        for (int c = 0; c < 4; c++) {
            int yi = y0 + (c >> 1);
            int xi = x0 + (c & 1);
            if (yi >= 0 && yi < HP && xi >= 0 && xi < HP) {
                const float* kr = qkv + ((long)(b * NTOK + yi * HP + xi)) * (3 * CDIM)
                                      + CDIM + h * HEADD;
                const float* vr = kr + CDIM;
                float wc = cw[c];
                k0 += wc * kr[lane];      k1 += wc * kr[lane + 32];
                v0 += wc * vr[lane];      v1 += wc * vr[lane + 32];
            }
        }
        sv0[p] = v0; sv1[p] = v1;
        float d = q0 * k0 + q1 * k1;
        #pragma unroll
        for (int off = 16; off; off >>= 1) d += __shfl_xor_sync(~0u, d, off);
        att[p] = d * SCALE_F;
    }

    float mx = fmaxf(fmaxf(att[0], att[1]), fmaxf(att[2], att[3]));
    float e[NPTS], sum = 0.f;
    #pragma unroll
    for (int p = 0; p < NPTS; p++) { e[p] = expf(att[p] - mx); sum += e[p]; }
    float inv = 1.f / sum;

    float o0 = 0.f, o1 = 0.f;
    #pragma unroll
    for (int p = 0; p < NPTS; p++) {
        float a = e[p] * inv;
        o0 += a * sv0[p];
        o1 += a * sv1[p];
    }
    long base = ((long)(b * NTOK + n)) * CDIM + h * HEADD;
    bf16 h0, l0, h1, l1;
    split_pair(o0, h0, l0);
    split_pair(o1, h1, l1);
    oh[base + lane]      = h0;  ol[base + lane]      = l0;
    oh[base + lane + 32] = h1;  ol[base + lane + 32] = l1;
}

// =====================================================================
// Output transpose: (B,N,C) -> (B,C,Hp,Wp)
// =====================================================================
__global__ void out_transpose_kernel(const float* __restrict__ x, float* __restrict__ out)
{
    long idx = (long)blockIdx.x * blockDim.x + threadIdx.x;
    if (idx >= (long)MROWS * CDIM) return;
    int n = (int)(idx % NTOK);
    int c = (int)((idx / NTOK) % CDIM);
    int b = (int)(idx / ((long)NTOK * CDIM));
    out[idx] = x[((long)(b * NTOK + n)) * CDIM + c];
}

// =====================================================================
// Host launcher
// =====================================================================
#define SMEM_BYTES (2 * 4 * STG_ARR * 2)   // 81920

extern "C" void kernel_launch(void* const* d_in, const int* in_sizes, int n_in,
                              void* d_out, int out_size)
{
    const float* x       = (const float*)d_in[0];
    const float* patch_w = (const float*)d_in[1];
    const float* patch_b = (const float*)d_in[2];
    const float* ln1_s   = (const float*)d_in[3];
    const float* ln1_b   = (const float*)d_in[4];
    const float* qkv_w   = (const float*)d_in[5];
    const float* offs_w  = (const float*)d_in[6];
    const float* offs_b  = (const float*)d_in[7];
    const float* proj_w  = (const float*)d_in[8];
    const float* proj_b  = (const float*)d_in[9];
    const float* ln2_s   = (const float*)d_in[10];
    const float* ln2_b   = (const float*)d_in[11];
    const float* fc1_w   = (const float*)d_in[12];
    const float* fc1_b   = (const float*)d_in[13];
    const float* fc2_w   = (const float*)d_in[14];
    const float* fc2_b   = (const float*)d_in[15];

    cudaFuncSetAttribute(mma_gemm_kernel,
                         cudaFuncAttributeMaxDynamicSharedMemorySize, SMEM_BYTES);

    float *gx, *gqkv, *goffs, *gsc;
    bf16 *ghh,*ghl,*gcolh,*gcoll,*gqkvh,*gqkvl,*gaoh,*gaol,*gsch,*gscl;
    bf16 *gmlph,*gmlpl,*gvth,*gvtl;
    bf16 *pwh,*pwl,*qwh,*qwl,*owh,*owl,*jwh,*jwl,*f1h,*f1l,*f2h,*f2l;
    cudaGetSymbolAddress((void**)&gx,    g_x);
    cudaGetSymbolAddress((void**)&gqkv,  g_qkv);
    cudaGetSymbolAddress((void**)&goffs, g_offs);
    cudaGetSymbolAddress((void**)&gsc,   g_sc);
    cudaGetSymbolAddress((void**)&ghh,   g_hh);   cudaGetSymbolAddress((void**)&ghl,   g_hl);
    cudaGetSymbolAddress((void**)&gcolh, g_colh); cudaGetSymbolAddress((void**)&gcoll, g_coll);
    cudaGetSymbolAddress((void**)&gqkvh, g_qkvh); cudaGetSymbolAddress((void**)&gqkvl, g_qkvl);
    cudaGetSymbolAddress((void**)&gaoh,  g_aoh);  cudaGetSymbolAddress((void**)&gaol,  g_aol);
    cudaGetSymbolAddress((void**)&gsch,  g_sch);  cudaGetSymbolAddress((void**)&gscl,  g_scl);
    cudaGetSymbolAddress((void**)&gmlph, g_mlph); cudaGetSymbolAddress((void**)&gmlpl, g_mlpl);
    cudaGetSymbolAddress((void**)&gvth,  g_vth);  cudaGetSymbolAddress((void**)&gvtl,  g_vtl);
    cudaGetSymbolAddress((void**)&pwh, g_pwh); cudaGetSymbolAddress((void**)&pwl, g_pwl);
    cudaGetSymbolAddress((void**)&qwh, g_qwh); cudaGetSymbolAddress((void**)&qwl, g_qwl);
    cudaGetSymbolAddress((void**)&owh, g_owh); cudaGetSymbolAddress((void**)&owl, g_owl);
    cudaGetSymbolAddress((void**)&jwh, g_jwh); cudaGetSymbolAddress((void**)&jwl, g_jwl);
    cudaGetSymbolAddress((void**)&f1h, g_f1h); cudaGetSymbolAddress((void**)&f1l, g_f1l);
    cudaGetSymbolAddress((void**)&f2h, g_f2h); cudaGetSymbolAddress((void**)&f2l, g_f2l);

    const int M = MROWS;

    // ---- weight conversion (per launch) ----
    {
        long n1 = (long)CDIM * CDIM;
        cvt_pair_kernel<<<(int)((n1 + 255) / 256), 256>>>(patch_w, pwh, pwl, n1);
        long n2 = 6L * 3 * CDIM * CDIM;
        cvt_pair_kernel<<<(int)((n2 + 255) / 256), 256>>>(qkv_w, qwh, qwl, n2);
        long n3 = 6L * 96 * CDIM;
        cvt_pair_kernel<<<(int)((n3 + 255) / 256), 256>>>(offs_w, owh, owl, n3);
        long n4 = 6L * CDIM * CDIM;
        cvt_pair_kernel<<<(int)((n4 + 255) / 256), 256>>>(proj_w, jwh, jwl, n4);
        long n5 = 6L * 4 * CDIM * CDIM;
        cvt_pair_kernel<<<(int)((n5 + 255) / 256), 256>>>(fc1_w, f1h, f1l, n5);
        cvt_pair_kernel<<<(int)((n5 + 255) / 256), 256>>>(fc2_w, f2h, f2l, n5);
    }

    // ---- patch embed ----
    im2col_kernel<<<(M * CDIM + 255) / 256, 256>>>(x, gcolh, gcoll);
    mma_gemm_kernel<<<dim3(CDIM / TBN, M / TBM, 1), 256, SMEM_BYTES>>>(
        gcolh, gcoll, pwh, pwl, gx, nullptr, nullptr, patch_b,
        M, CDIM, CDIM, CDIM, CDIM, CDIM,
        0, 0, 0, 0, 0, 0, 1, 0);

    for (int i = 0; i < 6; i++) {
        layernorm_kernel<<<M, 256>>>(gx, ghh, ghl, ln1_s + i * CDIM, ln1_b + i * CDIM);

        // QKV: f32 + pairs
        mma_gemm_kernel<<<dim3(2304 / TBN, M / TBM, 1), 256, SMEM_BYTES>>>(
            ghh, ghl, qwh + (long)i * 2304 * CDIM, qwl + (long)i * 2304 * CDIM,
            gqkv, gqkvh, gqkvl, nullptr,
            M, 2304, CDIM, CDIM, CDIM, 2304,
            0, 0, 0, 0, 0, 0, 1, 0);

        bool sample = ((i + 1) % 3) != 0;
        if (sample) {
            mma_gemm_kernel<<<dim3(1, M / TBM, 1), 256, SMEM_BYTES>>>(
                gqkvh, gqkvl, owh + (long)i * 96 * CDIM, owl + (long)i * 96 * CDIM,
                goffs, nullptr, nullptr, offs_b + i * 96,
                M, 96, CDIM, 3 * CDIM, CDIM, 96,
                0, 0, 0, 0, 0, 0, 1, 0);
            deform_attn_kernel<<<(BB * NHEADS * NTOK * 32) / 256, 256>>>(
                gqkv, goffs, gaoh, gaol);
        } else {
            vtrans_kernel<<<(BB * NHEADS * HEADD * NTOK + 255) / 256, 256>>>(
                gqkv, gvth, gvtl);
            // scores = q @ k^T
            mma_gemm_kernel<<<dim3(NTOK / TBN, NTOK / TBM, BB * NHEADS), 256, SMEM_BYTES>>>(
                gqkvh, gqkvl, gqkvh + CDIM, gqkvl + CDIM,
                gsc, nullptr, nullptr, nullptr,
                NTOK, NTOK, HEADD, 3 * CDIM, 3 * CDIM, NTOK,
                (long)NTOK * 3 * CDIM, HEADD,
                (long)NTOK * 3 * CDIM, HEADD,
                (long)NHEADS * NTOK * NTOK, (long)NTOK * NTOK,
                NHEADS, 0);
            softmax_kernel<<<BB * NHEADS * NTOK, 256>>>(gsc, gsch, gscl);
            // out = P @ V  via vT (N=64)
            mma_gemm_kernel<<<dim3(1, NTOK / TBM, BB * NHEADS), 256, SMEM_BYTES>>>(
                gsch, gscl, gvth, gvtl,
                nullptr, gaoh, gaol, nullptr,
                NTOK, HEADD, NTOK, NTOK, NTOK, CDIM,
                (long)NHEADS * NTOK * NTOK, (long)NTOK * NTOK,
                (long)NHEADS * HEADD * NTOK, (long)HEADD * NTOK,
                (long)NTOK * CDIM, HEADD,
                NHEADS, 0);
        }

        // proj + residual
        mma_gemm_kernel<<<dim3(CDIM / TBN, M / TBM, 1), 256, SMEM_BYTES>>>(
            gaoh, gaol, jwh + (long)i * CDIM * CDIM, jwl + (long)i * CDIM * CDIM,
            gx, nullptr, nullptr, proj_b + i * CDIM,
            M, CDIM, CDIM, CDIM, CDIM, CDIM,
            0, 0, 0, 0, 0, 0, 1, 2);

        layernorm_kernel<<<M, 256>>>(gx, ghh, ghl, ln2_s + i * CDIM, ln2_b + i * CDIM);

        // fc1 + gelu -> pairs
        mma_gemm_kernel<<<dim3(3072 / TBN, M / TBM, 1), 256, SMEM_BYTES>>>(
            ghh, ghl, f1h + (long)i * 3072 * CDIM, f1l + (long)i * 3072 * CDIM,
            nullptr, gmlph, gmlpl, fc1_b + i * 3072,
            M, 3072, CDIM, CDIM, CDIM, 3072,
            0, 0, 0, 0, 0, 0, 1, 1);
        // fc2 + residual
        mma_gemm_kernel<<<dim3(CDIM / TBN, M / TBM, 1), 256, SMEM_BYTES>>>(
            gmlph, gmlpl, f2h + (long)i * CDIM * 3072, f2l + (long)i * CDIM * 3072,
            gx, nullptr, nullptr, fc2_b + i * CDIM,
            M, CDIM, 3072, 3072, 3072, CDIM,
            0, 0, 0, 0, 0, 0, 1, 2);
    }

    out_transpose_kernel<<<(M * CDIM + 255) / 256, 256>>>(gx, (float*)d_out);
}